// round 8
// baseline (speedup 1.0000x reference)
#include <cuda_runtime.h>
#include <cuda_bf16.h>

#define NNODE 50000
#define HID   32
#define DIN   128
#define DOUT  16
#define NLAYER 15
#define MAXEDGE 900000   // E (800000) + N self-loops (50000), with margin

// ---------------- device scratch (no runtime allocation allowed) -------------
__device__ float g_h0[NNODE * HID];
__device__ float g_hpA[NNODE * HID];
__device__ float g_hpB[NNODE * HID];
__device__ float g_lsA[NNODE];
__device__ float g_rsA[NNODE];
__device__ float g_lsB[NNODE];
__device__ float g_rsB[NNODE];
__device__ int   g_cnt[NNODE];
__device__ int   g_rowp[NNODE + 1];
__device__ int   g_wr[NNODE];
__device__ int   g_col[MAXEDGE];

// ---------------- CSR build --------------------------------------------------
__global__ void k_init_cnt() {
    int i = blockIdx.x * blockDim.x + threadIdx.x;
    if (i < NNODE) g_cnt[i] = 1;   // self-loop
}

__global__ void k_count(const int* __restrict__ dst, int E) {
    int e = blockIdx.x * blockDim.x + threadIdx.x;
    if (e < E) atomicAdd(&g_cnt[dst[e]], 1);
}

// single-block chunked scan: row_ptr = exclusive prefix of cnt
__global__ void k_scan() {
    __shared__ int wsum[32];
    __shared__ int carry_sh;
    int tid = threadIdx.x;
    int lane = tid & 31, warp = tid >> 5;
    if (tid == 0) { carry_sh = 0; g_rowp[0] = 0; }
    __syncthreads();
    for (int base = 0; base < NNODE; base += 1024) {
        int i = base + tid;
        int v = (i < NNODE) ? g_cnt[i] : 0;
        int x = v;
        #pragma unroll
        for (int off = 1; off < 32; off <<= 1) {
            int t = __shfl_up_sync(0xFFFFFFFFu, x, off);
            if (lane >= off) x += t;
        }
        if (lane == 31) wsum[warp] = x;
        __syncthreads();
        if (warp == 0) {
            int w = wsum[lane];
            #pragma unroll
            for (int off = 1; off < 32; off <<= 1) {
                int t = __shfl_up_sync(0xFFFFFFFFu, w, off);
                if (lane >= off) w += t;
            }
            wsum[lane] = w;
        }
        __syncthreads();
        int incl = x + (warp > 0 ? wsum[warp - 1] : 0) + carry_sh;
        if (i < NNODE) g_rowp[i + 1] = incl;
        __syncthreads();
        if (tid == 1023) carry_sh = incl;
        __syncthreads();
    }
}

__global__ void k_copy_wr() {
    int i = blockIdx.x * blockDim.x + threadIdx.x;
    if (i < NNODE) g_wr[i] = g_rowp[i];
}

__global__ void k_scatter(const int* __restrict__ src, const int* __restrict__ dst, int E) {
    int idx = blockIdx.x * blockDim.x + threadIdx.x;
    if (idx < E) {
        int d = dst[idx];
        int pos = atomicAdd(&g_wr[d], 1);
        g_col[pos] = src[idx];
    } else if (idx < E + NNODE) {
        int i = idx - E;
        int pos = atomicAdd(&g_wr[i], 1);
        g_col[pos] = i;
    }
}

// ---------------- conv0: h0 = x @ W0 + b0 ------------------------------------
__global__ void k_conv0(const float* __restrict__ x, const float* __restrict__ W0,
                        const float* __restrict__ b0, float* __restrict__ h) {
    __shared__ float Ws[DIN * HID];   // 16 KB
    int tid = threadIdx.x;
    for (int i = tid; i < DIN * HID; i += 256) Ws[i] = W0[i];
    __syncthreads();
    int node = blockIdx.x * 8 + (tid >> 5);
    if (node >= NNODE) return;
    int lane = tid & 31;
    float xr[4];
    #pragma unroll
    for (int j = 0; j < 4; j++) xr[j] = x[node * DIN + j * 32 + lane];
    float acc = b0[lane];
    #pragma unroll
    for (int k = 0; k < DIN; k++) {
        float bv = __shfl_sync(0xFFFFFFFFu, xr[k >> 5], k & 31);
        acc += bv * Ws[k * HID + lane];
    }
    h[node * HID + lane] = acc;
}

// ------ transform0: hp = h0@W ; ls = hp.al ; rs = hp.ar  (layer 0 only) ------
__global__ void k_transform(const float* __restrict__ h, const float* __restrict__ W,
                            const float* __restrict__ al, const float* __restrict__ ar,
                            float* __restrict__ hp, float* __restrict__ ls,
                            float* __restrict__ rs) {
    __shared__ float Ws[HID * HID];
    __shared__ float als[HID], ars[HID];
    int tid = threadIdx.x;
    for (int i = tid; i < HID * HID; i += 256) Ws[i] = W[i];
    if (tid < HID) { als[tid] = al[tid]; ars[tid] = ar[tid]; }
    __syncthreads();
    int node = blockIdx.x * 8 + (tid >> 5);
    if (node >= NNODE) return;
    int lane = tid & 31;
    float hv = h[node * HID + lane];
    float acc = 0.f;
    #pragma unroll
    for (int k = 0; k < HID; k++) {
        float bv = __shfl_sync(0xFFFFFFFFu, hv, k);
        acc += bv * Ws[k * HID + lane];
    }
    hp[node * HID + lane] = acc;
    float pl = acc * als[lane];
    float pr = acc * ars[lane];
    #pragma unroll
    for (int off = 16; off >= 1; off >>= 1) {
        pl += __shfl_xor_sync(0xFFFFFFFFu, pl, off);
        pr += __shfl_xor_sync(0xFFFFFFFFu, pr, off);
    }
    if (lane == 0) { ls[node] = pl; rs[node] = pr; }
}

// -------- fused layer: softmax-aggregate + (next transform | conv16) ---------
// Warp per dst node, batches of 32 edges.
// Phase A (lanes=channels): COALESCED gather of source rows into smem (1 L1
//   wavefront per row instead of 8 scattered 16B wavefronts).
// Phase B (lanes=edges): per-edge dot + attention score from smem, batched
//   online-softmax reductions.
// Phase C (lanes=channels): acc += pe[j] * sR[j][lane], all smem, no shuffles.
// Epilogue: fused next-layer transform, or final conv16.
__global__ void k_fused(const float* __restrict__ hp_in,
                        const float* __restrict__ ls_in,
                        const float* __restrict__ rs_in,
                        const float* __restrict__ bias,     // bs[l]
                        const float* __restrict__ Wn,       // next W [32x32] or W16 [32x16]
                        const float* __restrict__ aln,      // next att_l (unused if final)
                        const float* __restrict__ arn,      // next att_r (unused if final)
                        const float* __restrict__ b16,      // final bias (unused if !final)
                        float* __restrict__ hp_out,         // next hp, or d_out if final
                        float* __restrict__ ls_out,
                        float* __restrict__ rs_out,
                        int final_flag) {
    __shared__ float sW[HID * HID];       // 4 KB
    __shared__ float sal[HID], sar[HID], sb[HID], sb16[DOUT];
    __shared__ float sHi[8][HID];         // per-warp dst row
    __shared__ float sR[8][32][HID + 1];  // gathered src rows, stride-33 pad (33.8 KB)
    __shared__ float sPe[8][32];
    __shared__ int   sIdx[8][32];
    int tid = threadIdx.x;
    int wid = tid >> 5, lane = tid & 31;

    if (final_flag) {
        for (int i = tid; i < HID * DOUT; i += 256) sW[i] = Wn[i];
        if (tid < DOUT) sb16[tid] = b16[tid];
    } else {
        for (int i = tid; i < HID * HID; i += 256) sW[i] = Wn[i];
        if (tid < HID) { sal[tid] = aln[tid]; sar[tid] = arn[tid]; }
    }
    if (tid < HID) sb[tid] = bias[tid];
    __syncthreads();

    int node = blockIdx.x * 8 + wid;
    if (node >= NNODE) return;

    sHi[wid][lane] = hp_in[node * HID + lane];
    float rs = rs_in[node];
    int beg = g_rowp[node], end = g_rowp[node + 1];
    float m = -1e30f, den = 0.f, acc = 0.f;

    for (int ebase = beg; ebase < end; ebase += 32) {
        int eid = ebase + lane;
        bool valid = (eid < end);
        int nb = min(32, end - ebase);
        int s = valid ? g_col[eid] : node;
        sIdx[wid][lane] = s;
        float lsv = ls_in[s];               // scattered scalar gather (lanes=edges)
        __syncwarp();

        // Phase A: coalesced row gather into smem (1 wavefront per row)
        #pragma unroll 4
        for (int j = 0; j < nb; j++) {
            int sj = sIdx[wid][j];          // LDS broadcast
            sR[wid][j][lane] = hp_in[sj * HID + lane];
        }
        __syncwarp();

        // Phase B: lane = edge, dot from smem
        float p = 0.f;
        #pragma unroll
        for (int c = 0; c < HID; c++)
            p += sHi[wid][c] * sR[wid][lane][c];
        float a = lsv + rs;
        a *= 1.f / (1.f + __expf(-p));       // * sigmoid(MX logit)
        a = (a >= 0.f) ? a : 0.2f * a;       // leaky_relu
        if (!valid) a = -1e30f;

        float bm = a;
        #pragma unroll
        for (int off = 16; off >= 1; off >>= 1)
            bm = fmaxf(bm, __shfl_xor_sync(0xFFFFFFFFu, bm, off));
        float nm = fmaxf(m, bm);
        float sc = __expf(m - nm);
        float pe = valid ? __expf(a - nm) : 0.f;
        sPe[wid][lane] = pe;
        float ps = pe;
        #pragma unroll
        for (int off = 16; off >= 1; off >>= 1)
            ps += __shfl_xor_sync(0xFFFFFFFFu, ps, off);
        den = den * sc + ps;
        acc *= sc;
        m = nm;
        __syncwarp();

        // Phase C: lane = channel, weighted aggregate from smem
        #pragma unroll 4
        for (int j = 0; j < nb; j++)
            acc += sPe[wid][j] * sR[wid][j][lane];
    }

    float o = acc / den + sb[lane];
    o = fmaxf(o, 0.f);                      // relu (every layer)

    if (!final_flag) {
        // fused next-layer transform: hp_next = o @ Wn ; ls/rs = hp_next . a{l,r}
        float hpn = 0.f;
        #pragma unroll
        for (int k = 0; k < HID; k++) {
            float bv = __shfl_sync(0xFFFFFFFFu, o, k);
            hpn += bv * sW[k * HID + lane];
        }
        hp_out[node * HID + lane] = hpn;
        float pl = hpn * sal[lane];
        float pr = hpn * sar[lane];
        #pragma unroll
        for (int off = 16; off >= 1; off >>= 1) {
            pl += __shfl_xor_sync(0xFFFFFFFFu, pl, off);
            pr += __shfl_xor_sync(0xFFFFFFFFu, pr, off);
        }
        if (lane == 0) { ls_out[node] = pl; rs_out[node] = pr; }
    } else {
        // fused conv16: out = o @ W16 + b16
        int oc = lane & (DOUT - 1);
        float a16 = 0.f;
        #pragma unroll
        for (int k = 0; k < HID; k++) {
            float bv = __shfl_sync(0xFFFFFFFFu, o, k);
            a16 += bv * sW[k * DOUT + oc];
        }
        if (lane < DOUT)
            hp_out[node * DOUT + lane] = a16 + sb16[lane];
    }
}

// ---------------- launch ------------------------------------------------------
extern "C" void kernel_launch(void* const* d_in, const int* in_sizes, int n_in,
                              void* d_out, int out_size) {
    const float* x    = (const float*)d_in[0];
    const int*   ei   = (const int*)d_in[1];
    const float* W0   = (const float*)d_in[2];
    const float* b0   = (const float*)d_in[3];
    const float* Ws   = (const float*)d_in[4];   // [L,H,H]
    const float* al   = (const float*)d_in[5];   // [L,H]
    const float* ar   = (const float*)d_in[6];   // [L,H]
    const float* bs   = (const float*)d_in[7];   // [L,H]
    const float* W16  = (const float*)d_in[8];
    const float* b16  = (const float*)d_in[9];
    float*       out  = (float*)d_out;

    const int E = in_sizes[1] / 2;
    const int* src = ei;
    const int* dst = ei + E;

    float *h0, *hpA, *hpB, *lsA, *lsB, *rsA, *rsB;
    cudaGetSymbolAddress((void**)&h0,  g_h0);
    cudaGetSymbolAddress((void**)&hpA, g_hpA);
    cudaGetSymbolAddress((void**)&hpB, g_hpB);
    cudaGetSymbolAddress((void**)&lsA, g_lsA);
    cudaGetSymbolAddress((void**)&lsB, g_lsB);
    cudaGetSymbolAddress((void**)&rsA, g_rsA);
    cudaGetSymbolAddress((void**)&rsB, g_rsB);

    const int TPB = 256;
    const int nodeBlocks = (NNODE + 7) / 8;

    // CSR build
    k_init_cnt<<<(NNODE + TPB - 1) / TPB, TPB>>>();
    k_count<<<(E + TPB - 1) / TPB, TPB>>>(dst, E);
    k_scan<<<1, 1024>>>();
    k_copy_wr<<<(NNODE + TPB - 1) / TPB, TPB>>>();
    k_scatter<<<(E + NNODE + TPB - 1) / TPB, TPB>>>(src, dst, E);

    // conv0 + transform for layer 0
    k_conv0<<<nodeBlocks, TPB>>>(x, W0, b0, h0);
    k_transform<<<nodeBlocks, TPB>>>(h0, Ws, al, ar, hpA, lsA, rsA);

    // 15 fused layers (agg_l + transform_{l+1}), final fuses conv16
    float *hp_in = hpA, *ls_in = lsA, *rs_in = rsA;
    float *hp_ot = hpB, *ls_ot = lsB, *rs_ot = rsB;
    for (int l = 0; l < NLAYER; l++) {
        int fin = (l == NLAYER - 1);
        k_fused<<<nodeBlocks, TPB>>>(
            hp_in, ls_in, rs_in, bs + l * HID,
            fin ? W16 : Ws + (l + 1) * HID * HID,
            fin ? al : al + (l + 1) * HID,      // dummy when final (unread)
            fin ? ar : ar + (l + 1) * HID,
            b16,
            fin ? out : hp_ot, ls_ot, rs_ot, fin);
        float* t;
        t = hp_in; hp_in = hp_ot; hp_ot = t;
        t = ls_in; ls_in = ls_ot; ls_ot = t;
        t = rs_in; rs_in = rs_ot; rs_ot = t;
    }
}

// round 11
// speedup vs baseline: 1.0584x; 1.0584x over previous
#include <cuda_runtime.h>
#include <cuda_bf16.h>

#define NNODE 50000
#define HID   32
#define DIN   128
#define DOUT  16
#define NLAYER 15
#define MAXEDGE 900000   // E (800000) + N self-loops (50000), with margin

// ---------------- device scratch (no runtime allocation allowed) -------------
__device__ float g_hpA[NNODE * HID];
__device__ float g_hpB[NNODE * HID];
__device__ float g_lsA[NNODE];
__device__ float g_rsA[NNODE];
__device__ float g_lsB[NNODE];
__device__ float g_rsB[NNODE];
__device__ int   g_cnt[NNODE];         // NNODE % 4 == 0 (int4 aligned)
__device__ int   g_rowp[NNODE + 4];
__device__ int   g_wr[NNODE];
__device__ int   g_col[MAXEDGE];

// ---------------- CSR build --------------------------------------------------
__global__ void k_init_cnt() {
    int i = blockIdx.x * blockDim.x + threadIdx.x;
    if (i < NNODE) g_cnt[i] = 1;   // self-loop
}

__global__ void k_count(const int* __restrict__ dst, int E) {
    int e = blockIdx.x * blockDim.x + threadIdx.x;
    if (e < E) atomicAdd(&g_cnt[dst[e]], 1);
}

// single-block int4 scan: g_rowp = exclusive prefix of cnt; also writes g_wr.
__global__ void k_scan() {
    __shared__ int wsum[32];
    __shared__ int carry_sh;
    int tid = threadIdx.x;
    int lane = tid & 31, warp = tid >> 5;
    if (tid == 0) { carry_sh = 0; g_rowp[0] = 0; }
    __syncthreads();
    const int NV4 = NNODE / 4;   // 12500
    for (int base = 0; base < NV4; base += 1024) {
        int i4 = base + tid;
        int4 v = (i4 < NV4) ? ((const int4*)g_cnt)[i4] : make_int4(0, 0, 0, 0);
        int tsum = v.x + v.y + v.z + v.w;
        int x = tsum;
        #pragma unroll
        for (int off = 1; off < 32; off <<= 1) {
            int t = __shfl_up_sync(0xFFFFFFFFu, x, off);
            if (lane >= off) x += t;
        }
        if (lane == 31) wsum[warp] = x;
        __syncthreads();
        if (warp == 0) {
            int w = wsum[lane];
            #pragma unroll
            for (int off = 1; off < 32; off <<= 1) {
                int t = __shfl_up_sync(0xFFFFFFFFu, w, off);
                if (lane >= off) w += t;
            }
            wsum[lane] = w;
        }
        __syncthreads();
        int excl = x - tsum + (warp > 0 ? wsum[warp - 1] : 0) + carry_sh;
        if (i4 < NV4) {
            int p1 = excl + v.x;
            int p2 = p1 + v.y;
            int p3 = p2 + v.z;
            int p4 = p3 + v.w;
            int e = i4 * 4;
            ((int4*)g_wr)[i4] = make_int4(excl, p1, p2, p3);
            g_rowp[e + 1] = p1; g_rowp[e + 2] = p2;
            g_rowp[e + 3] = p3; g_rowp[e + 4] = p4;
        }
        __syncthreads();
        if (tid == 0) carry_sh += wsum[31];
        __syncthreads();
    }
}

__global__ void k_scatter(const int* __restrict__ src, const int* __restrict__ dst, int E) {
    int idx = blockIdx.x * blockDim.x + threadIdx.x;
    if (idx < E) {
        int d = dst[idx];
        int pos = atomicAdd(&g_wr[d], 1);
        g_col[pos] = src[idx];
    } else if (idx < E + NNODE) {
        int i = idx - E;
        int pos = atomicAdd(&g_wr[i], 1);
        g_col[pos] = i;
    }
}

// ---- fused conv0 + transform0: hp = (x@W0+b0)@W ; ls/rs = hp . att_{l,r} ----
__global__ void k_conv0t(const float* __restrict__ x, const float* __restrict__ W0,
                         const float* __restrict__ b0, const float* __restrict__ W,
                         const float* __restrict__ al, const float* __restrict__ ar,
                         float* __restrict__ hp, float* __restrict__ ls,
                         float* __restrict__ rs) {
    __shared__ float W0s[DIN * HID];   // 16 KB
    __shared__ float Ws[HID * HID];    // 4 KB
    __shared__ float als[HID], ars[HID];
    int tid = threadIdx.x;
    for (int i = tid; i < DIN * HID; i += 256) W0s[i] = W0[i];
    for (int i = tid; i < HID * HID; i += 256) Ws[i] = W[i];
    if (tid < HID) { als[tid] = al[tid]; ars[tid] = ar[tid]; }
    __syncthreads();
    int node = blockIdx.x * 8 + (tid >> 5);
    if (node >= NNODE) return;
    int lane = tid & 31;
    float xr[4];
    #pragma unroll
    for (int j = 0; j < 4; j++) xr[j] = x[node * DIN + j * 32 + lane];
    float h0 = b0[lane];
    #pragma unroll
    for (int k = 0; k < DIN; k++) {
        float bv = __shfl_sync(0xFFFFFFFFu, xr[k >> 5], k & 31);
        h0 += bv * W0s[k * HID + lane];
    }
    float acc = 0.f;
    #pragma unroll
    for (int k = 0; k < HID; k++) {
        float bv = __shfl_sync(0xFFFFFFFFu, h0, k);
        acc += bv * Ws[k * HID + lane];
    }
    hp[node * HID + lane] = acc;
    float pl = acc * als[lane];
    float pr = acc * ars[lane];
    #pragma unroll
    for (int off = 16; off >= 1; off >>= 1) {
        pl += __shfl_xor_sync(0xFFFFFFFFu, pl, off);
        pr += __shfl_xor_sync(0xFFFFFFFFu, pr, off);
    }
    if (lane == 0) { ls[node] = pl; rs[node] = pr; }
}

// -------- fused layer: softmax-aggregate + (next transform | conv16) ---------
// Warp per dst node. Phase 1 (lanes = edges): per-edge dot via scattered
// float4 gather of the full source row, batched online softmax. Phase 2
// (lanes = channels): broadcast (pe, s) + coalesced (L1-hot) row reload.
// Epilogue: fused next-layer transform, or final conv16.
__global__ void k_fused(const float* __restrict__ hp_in,
                        const float* __restrict__ ls_in,
                        const float* __restrict__ rs_in,
                        const float* __restrict__ bias,     // bs[l]
                        const float* __restrict__ Wn,       // next W [32x32] or W16 [32x16]
                        const float* __restrict__ aln,      // next att_l (unused if final)
                        const float* __restrict__ arn,      // next att_r (unused if final)
                        const float* __restrict__ b16,      // final bias (unused if !final)
                        float* __restrict__ hp_out,         // next hp, or d_out if final
                        float* __restrict__ ls_out,
                        float* __restrict__ rs_out,
                        int final_flag) {
    __shared__ float sW[HID * HID];       // 4 KB
    __shared__ float sal[HID], sar[HID], sb[HID], sb16[DOUT];
    __shared__ float shi[8][HID];         // per-warp dst row
    int tid = threadIdx.x;
    int wid = tid >> 5, lane = tid & 31;

    if (final_flag) {
        for (int i = tid; i < HID * DOUT; i += 256) sW[i] = Wn[i];
        if (tid < DOUT) sb16[tid] = b16[tid];
    } else {
        for (int i = tid; i < HID * HID; i += 256) sW[i] = Wn[i];
        if (tid < HID) { sal[tid] = aln[tid]; sar[tid] = arn[tid]; }
    }
    if (tid < HID) sb[tid] = bias[tid];
    __syncthreads();

    int node = blockIdx.x * 8 + wid;
    if (node >= NNODE) return;

    float hi = hp_in[node * HID + lane];
    shi[wid][lane] = hi;
    __syncwarp();

    float rs = rs_in[node];
    int beg = g_rowp[node], end = g_rowp[node + 1];

    float m = -1e30f, den = 0.f, acc = 0.f;
    const float4* hi4 = (const float4*)shi[wid];

    for (int ebase = beg; ebase < end; ebase += 32) {
        int eid = ebase + lane;
        bool valid = (eid < end);
        int s = valid ? g_col[eid] : node;

        // per-lane edge: dot(hi, hp[s]) via vectorized gather
        const float4* row = (const float4*)(hp_in + s * HID);
        float p = 0.f;
        #pragma unroll
        for (int k = 0; k < HID / 4; k++) {
            float4 a4 = row[k];
            float4 b4 = hi4[k];
            p += a4.x * b4.x + a4.y * b4.y + a4.z * b4.z + a4.w * b4.w;
        }
        float a = ls_in[s] + rs;
        a *= 1.f / (1.f + __expf(-p));       // * sigmoid(MX logit)
        a = (a >= 0.f) ? a : 0.2f * a;       // leaky_relu
        if (!valid) a = -1e30f;

        // batch max + online rescale (once per 32 edges)
        float bm = a;
        #pragma unroll
        for (int off = 16; off >= 1; off >>= 1)
            bm = fmaxf(bm, __shfl_xor_sync(0xFFFFFFFFu, bm, off));
        float nm = fmaxf(m, bm);
        float sc = __expf(m - nm);
        float pe = valid ? __expf(a - nm) : 0.f;
        float ps = pe;
        #pragma unroll
        for (int off = 16; off >= 1; off >>= 1)
            ps += __shfl_xor_sync(0xFFFFFFFFu, ps, off);
        den = den * sc + ps;
        acc *= sc;
        m = nm;

        // lanes = channels: weighted aggregation (rows are L1-hot)
        int nb = min(32, end - ebase);
        for (int j = 0; j < nb; j++) {
            float pej = __shfl_sync(0xFFFFFFFFu, pe, j);
            int   sj  = __shfl_sync(0xFFFFFFFFu, s, j);
            acc += pej * hp_in[sj * HID + lane];
        }
    }

    float o = acc / den + sb[lane];
    o = fmaxf(o, 0.f);                      // relu (every layer)

    if (!final_flag) {
        // fused next-layer transform: hp_next = o @ Wn ; ls/rs = hp_next . a{l,r}
        float hpn = 0.f;
        #pragma unroll
        for (int k = 0; k < HID; k++) {
            float bv = __shfl_sync(0xFFFFFFFFu, o, k);
            hpn += bv * sW[k * HID + lane];
        }
        hp_out[node * HID + lane] = hpn;
        float pl = hpn * sal[lane];
        float pr = hpn * sar[lane];
        #pragma unroll
        for (int off = 16; off >= 1; off >>= 1) {
            pl += __shfl_xor_sync(0xFFFFFFFFu, pl, off);
            pr += __shfl_xor_sync(0xFFFFFFFFu, pr, off);
        }
        if (lane == 0) { ls_out[node] = pl; rs_out[node] = pr; }
    } else {
        // fused conv16: out = o @ W16 + b16
        int oc = lane & (DOUT - 1);
        float a16 = 0.f;
        #pragma unroll
        for (int k = 0; k < HID; k++) {
            float bv = __shfl_sync(0xFFFFFFFFu, o, k);
            a16 += bv * sW[k * DOUT + oc];
        }
        if (lane < DOUT)
            hp_out[node * DOUT + lane] = a16 + sb16[lane];
    }
}

// ---------------- launch ------------------------------------------------------
extern "C" void kernel_launch(void* const* d_in, const int* in_sizes, int n_in,
                              void* d_out, int out_size) {
    const float* x    = (const float*)d_in[0];
    const int*   ei   = (const int*)d_in[1];
    const float* W0   = (const float*)d_in[2];
    const float* b0   = (const float*)d_in[3];
    const float* Ws   = (const float*)d_in[4];   // [L,H,H]
    const float* al   = (const float*)d_in[5];   // [L,H]
    const float* ar   = (const float*)d_in[6];   // [L,H]
    const float* bs   = (const float*)d_in[7];   // [L,H]
    const float* W16  = (const float*)d_in[8];
    const float* b16  = (const float*)d_in[9];
    float*       out  = (float*)d_out;

    const int E = in_sizes[1] / 2;
    const int* src = ei;
    const int* dst = ei + E;

    float *hpA, *hpB, *lsA, *lsB, *rsA, *rsB;
    cudaGetSymbolAddress((void**)&hpA, g_hpA);
    cudaGetSymbolAddress((void**)&hpB, g_hpB);
    cudaGetSymbolAddress((void**)&lsA, g_lsA);
    cudaGetSymbolAddress((void**)&lsB, g_lsB);
    cudaGetSymbolAddress((void**)&rsA, g_rsA);
    cudaGetSymbolAddress((void**)&rsB, g_rsB);

    const int TPB = 256;
    const int nodeBlocks = (NNODE + 7) / 8;

    // CSR build (launches 0-3)
    k_init_cnt<<<(NNODE + TPB - 1) / TPB, TPB>>>();
    k_count<<<(E + TPB - 1) / TPB, TPB>>>(dst, E);
    k_scan<<<1, 1024>>>();                        // also seeds g_wr
    k_scatter<<<(E + NNODE + TPB - 1) / TPB, TPB>>>(src, dst, E);

    // fused conv0 + transform0 (launch 4)
    k_conv0t<<<nodeBlocks, TPB>>>(x, W0, b0, Ws, al, ar, hpA, lsA, rsA);

    // 15 fused layers (launches 5..19) — launch 5 is the ncu capture target
    float *hp_in = hpA, *ls_in = lsA, *rs_in = rsA;
    float *hp_ot = hpB, *ls_ot = lsB, *rs_ot = rsB;
    for (int l = 0; l < NLAYER; l++) {
        int fin = (l == NLAYER - 1);
        k_fused<<<nodeBlocks, TPB>>>(
            hp_in, ls_in, rs_in, bs + l * HID,
            fin ? W16 : Ws + (l + 1) * HID * HID,
            fin ? al : al + (l + 1) * HID,      // dummy when final (unread)
            fin ? ar : ar + (l + 1) * HID,
            b16,
            fin ? out : hp_ot, ls_ot, rs_ot, fin);
        float* t;
        t = hp_in; hp_in = hp_ot; hp_ot = t;
        t = ls_in; ls_in = ls_ot; ls_ot = t;
        t = rs_in; rs_in = rs_ot; rs_ot = t;
    }
}